// round 1
// baseline (speedup 1.0000x reference)
#include <cuda_runtime.h>
#include <stdint.h>

#define BB 8
#define NN 4096
#define DD 1024
#define HH 1024
#define NQ 64
#define TOPK 1024
#define SCALE_INV 0.03125f   // 1/sqrt(1024)

// ---------------- scratch (static device globals; no allocs allowed) ----------
__device__ float g_Qp_part[8 * NQ * DD];      // split-k partials for Qp
__device__ float g_Qp[NQ * DD];               // query_embed @ key_w^T   [q][d]
__device__ float g_qb[NQ];                    // query_embed @ key_b
__device__ float g_db[BB * NN];               // density bias per token
__device__ float g_S[BB * NQ * NN];           // attention scores [b][q][n]
__device__ float g_L[BB * NQ];                // logsumexp per (b,q) row
__device__ float g_t[BB * NN];                // max_q (s - L)  (monotone importance)
__device__ int   g_sel[BB * TOPK];            // selected indices, ascending

// ---------------- f32x2 helpers ----------------------------------------------
__device__ __forceinline__ unsigned long long pack2(float a, float b) {
    unsigned long long r;
    asm("mov.b64 %0, {%1,%2};" : "=l"(r) : "f"(a), "f"(b));
    return r;
}
__device__ __forceinline__ unsigned long long fma2(unsigned long long a,
                                                   unsigned long long b,
                                                   unsigned long long c) {
    unsigned long long d;
    asm("fma.rn.f32x2 %0, %1, %2, %3;" : "=l"(d) : "l"(a), "l"(b), "l"(c));
    return d;
}
__device__ __forceinline__ void unpack2(unsigned long long v, float& lo, float& hi) {
    asm("mov.b64 {%0,%1}, %2;" : "=f"(lo), "=f"(hi) : "l"(v));
}

// ---------------- K1a: Qp split-k partials ------------------------------------
// grid (64 d-tiles of 16, 8 k-splits of 128), block 256
__global__ void k_qp_part(const float* __restrict__ qe, const float* __restrict__ kw) {
    __shared__ float qe_s[64 * 129];
    __shared__ float kw_s[16 * 129];
    int t = threadIdx.x;
    int d0 = blockIdx.x * 16;
    int k0 = blockIdx.y * 128;
    #pragma unroll
    for (int i = 0; i < 32; i++) {
        int idx = t + i * 256;
        int q = idx >> 7, k = idx & 127;
        qe_s[q * 129 + k] = qe[q * HH + k0 + k];
    }
    #pragma unroll
    for (int i = 0; i < 8; i++) {
        int idx = t + i * 256;
        int d = idx >> 7, k = idx & 127;
        kw_s[d * 129 + k] = kw[(size_t)(d0 + d) * HH + k0 + k];
    }
    __syncthreads();
    int tq = t & 63, tg = t >> 6;
    float acc[4] = {0.f, 0.f, 0.f, 0.f};
    for (int k = 0; k < 128; k++) {
        float qv = qe_s[tq * 129 + k];
        #pragma unroll
        for (int i = 0; i < 4; i++)
            acc[i] = fmaf(qv, kw_s[(tg * 4 + i) * 129 + k], acc[i]);
    }
    #pragma unroll
    for (int i = 0; i < 4; i++)
        g_Qp_part[(size_t)blockIdx.y * (NQ * DD) + tq * DD + d0 + tg * 4 + i] = acc[i];
}

// ---------------- K1b: reduce split-k ----------------------------------------
__global__ void k_qp_reduce() {
    int idx = blockIdx.x * 256 + threadIdx.x;   // 65536 total
    float s = 0.f;
    #pragma unroll
    for (int j = 0; j < 8; j++) s += g_Qp_part[(size_t)j * (NQ * DD) + idx];
    g_Qp[idx] = s;
}

// ---------------- K1c: qb = qe @ key_b ----------------------------------------
__global__ void k_qb(const float* __restrict__ qe, const float* __restrict__ kb) {
    __shared__ float red[128];
    int q = blockIdx.x, t = threadIdx.x;
    float s = 0.f;
    for (int h = t; h < HH; h += 128) s += qe[q * HH + h] * kb[h];
    red[t] = s; __syncthreads();
    for (int o = 64; o > 0; o >>= 1) {
        if (t < o) red[t] += red[t + o];
        __syncthreads();
    }
    if (t == 0) g_qb[q] = red[0];
}

// ---------------- K2: density encoder bias ------------------------------------
__global__ void k_density(const float* __restrict__ dens,
                          const float* __restrict__ w1, const float* __restrict__ b1,
                          const float* __restrict__ w2, const float* __restrict__ b2) {
    __shared__ float s_w1[2048], s_b1[2048], s_w2[2048];
    int t = threadIdx.x;
    for (int i = t; i < 2048; i += 256) { s_w1[i] = w1[i]; s_b1[i] = b1[i]; s_w2[i] = w2[i]; }
    __syncthreads();
    int idx = blockIdx.x * 256 + t;             // < 32768
    float d = dens[idx];
    float acc = b2[0];
    #pragma unroll 4
    for (int j = 0; j < 2048; j++) {
        float h = fmaxf(fmaf(d, s_w1[j], s_b1[j]), 0.f);
        acc = fmaf(h, s_w2[j], acc);
    }
    g_db[idx] = acc;
}

// ---------------- K3: scores GEMM  S[b,q,n] -----------------------------------
// grid (32 n-tiles of 128, 8 b), block 256. Thread tile 8q x 4n via f32x2.
#define TFS 132
__global__ __launch_bounds__(256) void k_scores(const float* __restrict__ tf) {
    __shared__ __align__(16) float tf_s[16 * TFS];   // [kk][n], padded rows
    __shared__ __align__(16) float qp_s[16 * 64];    // [kk][q]
    int t = threadIdx.x;
    int n0 = blockIdx.x * 128;
    int b  = blockIdx.y;
    int qg = t >> 5, lane = t & 31;
    const float* tfb = tf + (size_t)b * NN * DD;

    unsigned long long acc[8][2];
    #pragma unroll
    for (int i = 0; i < 8; i++) { acc[i][0] = 0ull; acc[i][1] = 0ull; }

    for (int k0 = 0; k0 < DD; k0 += 16) {
        // load tf chunk: 128 rows x 16 k  ->  k-major smem
        #pragma unroll
        for (int r = 0; r < 2; r++) {
            int f = t + r * 256;
            int n = f >> 2, kq = (f & 3) * 4;
            float4 v = *(const float4*)(tfb + (size_t)(n0 + n) * DD + k0 + kq);
            tf_s[(kq + 0) * TFS + n] = v.x;
            tf_s[(kq + 1) * TFS + n] = v.y;
            tf_s[(kq + 2) * TFS + n] = v.z;
            tf_s[(kq + 3) * TFS + n] = v.w;
        }
        // load Qp chunk: 64 rows x 16 k -> k-major smem (256 float4 exactly)
        {
            int q = t >> 2, kq = (t & 3) * 4;
            float4 v = *(const float4*)(g_Qp + (size_t)q * DD + k0 + kq);
            qp_s[(kq + 0) * 64 + q] = v.x;
            qp_s[(kq + 1) * 64 + q] = v.y;
            qp_s[(kq + 2) * 64 + q] = v.z;
            qp_s[(kq + 3) * 64 + q] = v.w;
        }
        __syncthreads();
        #pragma unroll
        for (int kk = 0; kk < 16; kk++) {
            float4 tv = *(const float4*)&tf_s[kk * TFS + lane * 4];
            unsigned long long t01 = pack2(tv.x, tv.y);
            unsigned long long t23 = pack2(tv.z, tv.w);
            float4 qa = *(const float4*)&qp_s[kk * 64 + qg * 8];
            float4 qc = *(const float4*)&qp_s[kk * 64 + qg * 8 + 4];
            float qv[8] = {qa.x, qa.y, qa.z, qa.w, qc.x, qc.y, qc.z, qc.w};
            #pragma unroll
            for (int i = 0; i < 8; i++) {
                unsigned long long qd = pack2(qv[i], qv[i]);
                acc[i][0] = fma2(qd, t01, acc[i][0]);
                acc[i][1] = fma2(qd, t23, acc[i][1]);
            }
        }
        __syncthreads();
    }

    float4 dbv = *(const float4*)(g_db + b * NN + n0 + lane * 4);
    float dbx[4] = {dbv.x, dbv.y, dbv.z, dbv.w};
    #pragma unroll
    for (int i = 0; i < 8; i++) {
        int q = qg * 8 + i;
        float qb = g_qb[q];
        float a0, a1, a2, a3;
        unpack2(acc[i][0], a0, a1);
        unpack2(acc[i][1], a2, a3);
        float4 out;
        out.x = (a0 + qb) * SCALE_INV + dbx[0];
        out.y = (a1 + qb) * SCALE_INV + dbx[1];
        out.z = (a2 + qb) * SCALE_INV + dbx[2];
        out.w = (a3 + qb) * SCALE_INV + dbx[3];
        *(float4*)(g_S + ((size_t)(b * NQ + q)) * NN + n0 + lane * 4) = out;
    }
}

// ---------------- K4a: per-(b,q) logsumexp ------------------------------------
__global__ void k_logsum() {
    __shared__ float red[256];
    int row = blockIdx.x;                       // b*64+q
    const float* s = g_S + (size_t)row * NN;
    int t = threadIdx.x;
    float m = -1e30f;
    for (int i = t; i < NN; i += 256) m = fmaxf(m, s[i]);
    red[t] = m; __syncthreads();
    for (int o = 128; o > 0; o >>= 1) { if (t < o) red[t] = fmaxf(red[t], red[t + o]); __syncthreads(); }
    m = red[0]; __syncthreads();
    float sum = 0.f;
    for (int i = t; i < NN; i += 256) sum += __expf(s[i] - m);
    red[t] = sum; __syncthreads();
    for (int o = 128; o > 0; o >>= 1) { if (t < o) red[t] += red[t + o]; __syncthreads(); }
    if (t == 0) g_L[row] = m + logf(red[0]);
}

// ---------------- K4b: t[b,n] = max_q (s - L[q]) -------------------------------
__global__ void k_importance() {
    __shared__ float Ls[NQ];
    int b = blockIdx.y;
    int n = blockIdx.x * 256 + threadIdx.x;
    if (threadIdx.x < NQ) Ls[threadIdx.x] = g_L[b * NQ + threadIdx.x];
    __syncthreads();
    const float* s = g_S + (size_t)b * NQ * NN;
    float m = -1e30f;
    #pragma unroll 8
    for (int q = 0; q < NQ; q++) m = fmaxf(m, s[(size_t)q * NN + n] - Ls[q]);
    g_t[b * NN + n] = m;
}

// ---------------- K5: exact top-1024 + ascending-index compaction --------------
// one block per batch, 1024 threads
__global__ __launch_bounds__(1024) void k_select() {
    __shared__ unsigned key[NN];
    __shared__ int hist[16];
    __shared__ int sg[1024], se[1024];
    __shared__ unsigned s_p;
    __shared__ int s_k;
    int b = blockIdx.x, t = threadIdx.x;

    for (int i = t; i < NN; i += 1024) {
        unsigned x = __float_as_uint(g_t[b * NN + i]);
        key[i] = x ^ ((unsigned)((int)x >> 31) | 0x80000000u);  // order-preserving
    }
    if (t == 0) { s_p = 0u; s_k = TOPK; }
    __syncthreads();

    // 4-bit radix select of the TOPK-th largest key
    for (int shift = 28; shift >= 0; shift -= 4) {
        if (t < 16) hist[t] = 0;
        __syncthreads();
        unsigned p = s_p;
        unsigned hm = (shift == 28) ? 0u : (0xFFFFFFFFu << (shift + 4));
        #pragma unroll
        for (int i = 0; i < 4; i++) {
            unsigned kx = key[t * 4 + i];
            if ((kx & hm) == (p & hm))
                atomicAdd(&hist[(kx >> shift) & 15], 1);
        }
        __syncthreads();
        if (t == 0) {
            int k = s_k, bin;
            for (bin = 15; bin > 0; bin--) {
                int c = hist[bin];
                if (k <= c) break;
                k -= c;
            }
            s_p = p | ((unsigned)bin << shift);
            s_k = k;
        }
        __syncthreads();
    }
    unsigned thr = s_p;
    int eq_need = s_k;   // # of threshold-equal tokens to take (lowest indices first)

    // predicates + per-thread sums over contiguous 4-element chunk
    int gl[4], el[4], gs = 0, es = 0;
    #pragma unroll
    for (int i = 0; i < 4; i++) {
        unsigned kx = key[t * 4 + i];
        gl[i] = kx > thr; el[i] = (kx == thr);
        gs += gl[i]; es += el[i];
    }
    sg[t] = gs; se[t] = es; __syncthreads();
    // block inclusive scan (Hillis-Steele)
    for (int off = 1; off < 1024; off <<= 1) {
        int vg = (t >= off) ? sg[t - off] : 0;
        int ve = (t >= off) ? se[t - off] : 0;
        __syncthreads();
        sg[t] += vg; se[t] += ve;
        __syncthreads();
    }
    int exg = sg[t] - gs, exe = se[t] - es;
    #pragma unroll
    for (int i = 0; i < 4; i++) {
        int n = t * 4 + i;
        bool sel = gl[i] || (el[i] && exe < eq_need);
        if (sel) {
            int pos = exg + min(exe, eq_need);
            g_sel[b * TOPK + pos] = n;
        }
        exg += gl[i]; exe += el[i];
    }
}

// ---------------- K6: gather selected rows ------------------------------------
// grid (1024, 8), block 256: one row (1024 floats) per block via float4
__global__ void k_gather(const float* __restrict__ tf, float* __restrict__ out) {
    int b = blockIdx.y, i = blockIdx.x;
    int row = g_sel[b * TOPK + i];
    const float4* src = (const float4*)(tf + ((size_t)b * NN + row) * DD);
    float4* dst = (float4*)(out + ((size_t)b * TOPK + i) * DD);
    dst[threadIdx.x] = src[threadIdx.x];
}

// ---------------- launch -------------------------------------------------------
extern "C" void kernel_launch(void* const* d_in, const int* in_sizes, int n_in,
                              void* d_out, int out_size) {
    const float* tf   = (const float*)d_in[0];   // token_features   [8,4096,1024]
    const float* dens = (const float*)d_in[1];   // token_densities  [8,4096]
    const float* qe   = (const float*)d_in[2];   // query_embed      [64,1024]
    const float* kw   = (const float*)d_in[3];   // key_w            [1024,1024]
    const float* kb   = (const float*)d_in[4];   // key_b            [1024]
    const float* w1   = (const float*)d_in[5];   // de_w1            [1,2048]
    const float* b1   = (const float*)d_in[6];   // de_b1            [2048]
    const float* w2   = (const float*)d_in[7];   // de_w2            [2048,1]
    const float* b2   = (const float*)d_in[8];   // de_b2            [1]
    float* out = (float*)d_out;                  // [8,1024,1024]

    k_qp_part<<<dim3(64, 8), 256>>>(qe, kw);
    k_qp_reduce<<<256, 256>>>();
    k_qb<<<64, 128>>>(qe, kb);
    k_density<<<128, 256>>>(dens, w1, b1, w2, b2);
    k_scores<<<dim3(32, 8), 256>>>(tf);
    k_logsum<<<BB * NQ, 256>>>();
    k_importance<<<dim3(16, 8), 256>>>();
    k_select<<<BB, 1024>>>();
    k_gather<<<dim3(TOPK, BB), 256>>>(tf, out);
}